// round 6
// baseline (speedup 1.0000x reference)
#include <cuda_runtime.h>

#define NB      16384
#define NA      64
#define DIN     128
#define NH1     32
#define NH2     16
#define NITERS  200
#define POW_ITERS 120

#define FW      8      // warps per fista block
#define RPW     4      // rows per warp
#define NPAIR   (RPW/2)
#define RPB     (FW * RPW)

typedef unsigned long long u64;

__device__ float g_step;
__device__ float g_p[NB * NA];

__device__ __forceinline__ u64 pack2(float x, float y) {
    u64 r; asm("mov.b64 %0, {%1,%2};" : "=l"(r) : "f"(x), "f"(y)); return r;
}
__device__ __forceinline__ void unpack2(u64 v, float& x, float& y) {
    asm("mov.b64 {%0,%1}, %2;" : "=f"(x), "=f"(y) : "l"(v));
}
__device__ __forceinline__ u64 ffma2(u64 a, u64 b, u64 c) {
    u64 d; asm("fma.rn.f32x2 %0, %1, %2, %3;" : "=l"(d) : "l"(a), "l"(b), "l"(c)); return d;
}
__device__ __forceinline__ float warpsum(float v) {
    #pragma unroll
    for (int o = 16; o > 0; o >>= 1) v += __shfl_xor_sync(0xffffffffu, v, o);
    return v;
}

// ---------------------------------------------------------------------------
// Kernel 1: lambda_max(sigma) via power iteration, single warp.
// Lane handles rows (lane, lane+32). sigma rows padded to stride 68 so the
// per-lane float4 row loads are bank-conflict-free.
// ---------------------------------------------------------------------------
__global__ void power_kernel(const float* __restrict__ sigma) {
    __shared__ __align__(16) float sig[NA * 68];
    __shared__ __align__(16) float vs[NA];
    int lane = threadIdx.x;

    for (int i = lane; i < NA * NA; i += 32)
        sig[(i >> 6) * 68 + (i & 63)] = sigma[i];
    vs[lane] = 1.0f;
    vs[lane + 32] = 1.0f;
    __syncwarp();

    float lambda = 1.0f;
    const float* row0 = &sig[lane * 68];
    const float* row1 = &sig[(lane + 32) * 68];
    #pragma unroll 1
    for (int it = 0; it < POW_ITERS; ++it) {
        float a = 0.f, b = 0.f;
        #pragma unroll
        for (int kq = 0; kq < 16; ++kq) {
            float4 vv = *reinterpret_cast<const float4*>(&vs[kq * 4]);
            float4 s0 = *reinterpret_cast<const float4*>(&row0[kq * 4]);
            float4 s1 = *reinterpret_cast<const float4*>(&row1[kq * 4]);
            a = fmaf(s0.x, vv.x, a); a = fmaf(s0.y, vv.y, a);
            a = fmaf(s0.z, vv.z, a); a = fmaf(s0.w, vv.w, a);
            b = fmaf(s1.x, vv.x, b); b = fmaf(s1.y, vv.y, b);
            b = fmaf(s1.z, vv.z, b); b = fmaf(s1.w, vv.w, b);
        }
        float dt = vs[lane] * a + vs[lane + 32] * b;   // Rayleigh numerator
        float nr = a * a + b * b;
        dt = warpsum(dt);
        nr = warpsum(nr);
        lambda = dt;                                    // v unit-norm for it>=1
        float rinv = rsqrtf(nr);
        __syncwarp();
        vs[lane] = a * rinv;
        vs[lane + 32] = b * rinv;
        __syncwarp();
    }
    if (lane == 0) g_step = 1.0f / lambda;
}

// ---------------------------------------------------------------------------
// Kernel 2: MLP -> mu (output) and p = -gamma*mu (scratch). Warp per row.
// ---------------------------------------------------------------------------
__global__ __launch_bounds__(256) void mlp_kernel(
    const float* __restrict__ x,  const float* __restrict__ W1, const float* __restrict__ b1,
    const float* __restrict__ W2, const float* __restrict__ b2,
    const float* __restrict__ W3, const float* __restrict__ b3,
    const float* __restrict__ gamma, float* __restrict__ out_mu)
{
    __shared__ float W1s[DIN * NH1];
    __shared__ float W2s[NH1 * NH2];
    __shared__ float W3s[NH2 * NA];
    __shared__ float b1s[NH1], b2s[NH2], b3s[NA];
    __shared__ __align__(16) float xs[8][DIN];
    __shared__ float h1s[8][NH1];
    __shared__ float h2s[8][NH2];

    int tid = threadIdx.x;
    for (int i = tid; i < DIN * NH1; i += 256) W1s[i] = W1[i];
    for (int i = tid; i < NH1 * NH2; i += 256) W2s[i] = W2[i];
    for (int i = tid; i < NH2 * NA;  i += 256) W3s[i] = W3[i];
    if (tid < NH1) b1s[tid] = b1[tid];
    if (tid < NH2) b2s[tid] = b2[tid];
    if (tid < NA)  b3s[tid] = b3[tid];
    __syncthreads();

    int warp = tid >> 5, lane = tid & 31;
    int row = blockIdx.x * 8 + warp;
    float g = gamma[0];

    #pragma unroll
    for (int q = 0; q < 4; ++q)
        xs[warp][lane + 32 * q] = x[row * DIN + lane + 32 * q];
    __syncwarp();

    float acc = b1s[lane];
    #pragma unroll
    for (int d = 0; d < DIN; d += 4) {
        float4 xv = *reinterpret_cast<const float4*>(&xs[warp][d]);
        acc = fmaf(xv.x, W1s[(d + 0) * NH1 + lane], acc);
        acc = fmaf(xv.y, W1s[(d + 1) * NH1 + lane], acc);
        acc = fmaf(xv.z, W1s[(d + 2) * NH1 + lane], acc);
        acc = fmaf(xv.w, W1s[(d + 3) * NH1 + lane], acc);
    }
    h1s[warp][lane] = fmaxf(acc, 0.0f);
    __syncwarp();

    if (lane < NH2) {
        float a2 = b2s[lane];
        #pragma unroll
        for (int d = 0; d < NH1; ++d)
            a2 = fmaf(h1s[warp][d], W2s[d * NH2 + lane], a2);
        h2s[warp][lane] = fmaxf(a2, 0.0f);
    }
    __syncwarp();

    float m0 = b3s[lane], m1 = b3s[lane + 32];
    #pragma unroll
    for (int d = 0; d < NH2; ++d) {
        float h = h2s[warp][d];
        m0 = fmaf(h, W3s[d * NA + lane], m0);
        m1 = fmaf(h, W3s[d * NA + lane + 32], m1);
    }
    out_mu[row * NA + lane]      = m0;
    out_mu[row * NA + lane + 32] = m1;
    g_p[row * NA + lane]      = -g * m0;
    g_p[row * NA + lane + 32] = -g * m1;
}

// ---------------------------------------------------------------------------
// Kernel 3: FISTA. Row-pair packed f32x2 matvec + Michelot projection with
// ballot-based counting and incremental sums.
//
// Layouts (per warp, lane j owns components j and j+32 of each row):
//   sigq[kp*64 + j]   = (s[2kp][j], s[2kp][j], s[2kp+1][j], s[2kp+1][j])
//   ydup[w][p][k]     = (y[row 2p][k], y[row 2p+1][k])   k = 0..63
// Accumulators glo[p] = (g_{2p}[j], g_{2p+1}[j]), ghi for j+32.
// ---------------------------------------------------------------------------
__global__ __launch_bounds__(256) void fista_kernel(
    const float* __restrict__ sigma, float* __restrict__ out_w)
{
    __shared__ __align__(16) float4 sigq[32 * 64];       // 32 KB
    __shared__ __align__(16) u64 ydup[FW][NPAIR][NA];    // 8 KB

    int tid = threadIdx.x;
    int warp = tid >> 5, lane = tid & 31;

    for (int i = tid; i < 32 * 64; i += 256) {
        int kp = i >> 6, j = i & 63;
        float s0 = sigma[(2 * kp) * NA + j];
        float s1 = sigma[(2 * kp + 1) * NA + j];
        sigq[i] = make_float4(s0, s0, s1, s1);
    }
    __syncthreads();

    float step = g_step;
    int row0 = blockIdx.x * RPB + warp * RPW;

    float px[RPW], py[RPW], wx[RPW], wy[RPW], yx[RPW], yy[RPW];
    #pragma unroll
    for (int r = 0; r < RPW; ++r) {
        px[r] = g_p[(row0 + r) * NA + lane];
        py[r] = g_p[(row0 + r) * NA + lane + 32];
        wx[r] = wy[r] = yx[r] = yy[r] = 1.0f / 64.0f;
    }
    float t = 1.0f;

    #pragma unroll 1
    for (int it = 0; it < NITERS; ++it) {
        __syncwarp();
        #pragma unroll
        for (int p = 0; p < NPAIR; ++p) {
            ydup[warp][p][lane]      = pack2(yx[2 * p], yx[2 * p + 1]);
            ydup[warp][p][lane + 32] = pack2(yy[2 * p], yy[2 * p + 1]);
        }
        __syncwarp();

        // grad = y @ sigma + p  (f32x2, rows packed in pairs)
        u64 glo[NPAIR], ghi[NPAIR];
        #pragma unroll
        for (int p = 0; p < NPAIR; ++p) {
            glo[p] = pack2(px[2 * p], px[2 * p + 1]);
            ghi[p] = pack2(py[2 * p], py[2 * p + 1]);
        }

        #pragma unroll
        for (int kp = 0; kp < 32; ++kp) {
            ulonglong2 sq0 = *reinterpret_cast<const ulonglong2*>(&sigq[kp * 64 + lane]);
            ulonglong2 sq1 = *reinterpret_cast<const ulonglong2*>(&sigq[kp * 64 + lane + 32]);
            #pragma unroll
            for (int p = 0; p < NPAIR; ++p) {
                ulonglong2 yb = *reinterpret_cast<const ulonglong2*>(&ydup[warp][p][2 * kp]);
                glo[p] = ffma2(yb.x, sq0.x, glo[p]);
                glo[p] = ffma2(yb.y, sq0.y, glo[p]);
                ghi[p] = ffma2(yb.x, sq1.x, ghi[p]);
                ghi[p] = ffma2(yb.y, sq1.y, ghi[p]);
            }
        }

        float gx[RPW], gy[RPW];
        #pragma unroll
        for (int p = 0; p < NPAIR; ++p) {
            unpack2(glo[p], gx[2 * p], gx[2 * p + 1]);
            unpack2(ghi[p], gy[2 * p], gy[2 * p + 1]);
        }

        float tn = 0.5f * (1.0f + sqrtf(1.0f + 4.0f * t * t));
        float beta = (t - 1.0f) / tn;
        t = tn;

        // ---- simplex projection (Michelot), all rows interleaved ----
        float vx[RPW], vy[RPW], S[RPW];
        int C[RPW];
        bool ax[RPW], ay[RPW], act[RPW];
        #pragma unroll
        for (int r = 0; r < RPW; ++r) {
            vx[r] = fmaf(-step, gx[r], yx[r]);
            vy[r] = fmaf(-step, gy[r], yy[r]);
            S[r] = warpsum(vx[r] + vy[r]);
            C[r] = 64;
            ax[r] = ay[r] = act[r] = true;
        }

        #pragma unroll 1
        while (act[0] | act[1] | act[2] | act[3]) {
            #pragma unroll
            for (int r = 0; r < RPW; ++r) {
                if (act[r]) {
                    float th = __fdividef(S[r] - 1.0f, (float)C[r]);
                    bool rx = ax[r] && (vx[r] <= th);
                    bool ry = ay[r] && (vy[r] <= th);
                    unsigned bx = __ballot_sync(0xffffffffu, rx);
                    unsigned by = __ballot_sync(0xffffffffu, ry);
                    if ((bx | by) == 0u) {
                        act[r] = false;
                    } else {
                        float rs = (rx ? vx[r] : 0.0f) + (ry ? vy[r] : 0.0f);
                        S[r] -= warpsum(rs);
                        C[r] -= __popc(bx) + __popc(by);
                        ax[r] = ax[r] && !rx;
                        ay[r] = ay[r] && !ry;
                    }
                }
            }
        }

        #pragma unroll
        for (int r = 0; r < RPW; ++r) {
            float th = (S[r] - 1.0f) / (float)C[r];      // precise final theta
            float wnx = ax[r] ? (vx[r] - th) : 0.0f;
            float wny = ay[r] ? (vy[r] - th) : 0.0f;
            yx[r] = fmaf(beta, wnx - wx[r], wnx);
            yy[r] = fmaf(beta, wny - wy[r], wny);
            wx[r] = wnx;
            wy[r] = wny;
        }
    }

    #pragma unroll
    for (int r = 0; r < RPW; ++r) {
        out_w[(row0 + r) * NA + lane]      = wx[r];
        out_w[(row0 + r) * NA + lane + 32] = wy[r];
    }
}

// ---------------------------------------------------------------------------
extern "C" void kernel_launch(void* const* d_in, const int* in_sizes, int n_in,
                              void* d_out, int out_size) {
    const float* x     = (const float*)d_in[0];
    const float* W1    = (const float*)d_in[1];
    const float* b1    = (const float*)d_in[2];
    const float* W2    = (const float*)d_in[3];
    const float* b2    = (const float*)d_in[4];
    const float* W3    = (const float*)d_in[5];
    const float* b3    = (const float*)d_in[6];
    const float* sigma = (const float*)d_in[7];
    const float* gamma = (const float*)d_in[8];

    float* out    = (float*)d_out;
    float* out_w  = out;                 // weights: [B, 64]
    float* out_mu = out + NB * NA;       // mu:      [B, 64]

    power_kernel<<<1, 32>>>(sigma);
    mlp_kernel<<<NB / 8, 256>>>(x, W1, b1, W2, b2, W3, b3, gamma, out_mu);
    fista_kernel<<<NB / RPB, 256>>>(sigma, out_w);
}